// round 7
// baseline (speedup 1.0000x reference)
#include <cuda_runtime.h>

#define B_  4
#define N_  16384
#define M_  4096
#define K_  16
#define R2  0.25f
#define NQ  (B_ * M_)

// Scratch: (x, y, z, |p|^2) per point. 4*16384*16B = 1 MB.
__device__ float4       g_pts[B_ * N_];
__device__ unsigned int g_qctr;   // work-stealing queue head

__global__ __launch_bounds__(256) void prep_kernel(const float* __restrict__ xyz) {
    int i = blockIdx.x * blockDim.x + threadIdx.x;
    if (i == 0) g_qctr = 0;       // reset queue every launch (graph replay safe)
    if (i < B_ * N_) {
        float x = xyz[3 * i + 0];
        float y = xyz[3 * i + 1];
        float z = xyz[3 * i + 2];
        // match jnp.sum(x**2,-1): (x*x + y*y) + z*z, no fma contraction
        float sq = __fadd_rn(__fadd_rn(__fmul_rn(x, x), __fmul_rn(y, y)), __fmul_rn(z, z));
        g_pts[i] = make_float4(x, y, z, sq);
    }
}

// DO NOT change: reproduces reference's expanded |q|^2+|p|^2-2qp arithmetic;
// determines boundary membership (rel_err).
__device__ __forceinline__ float dist2(float4 q, float4 p) {
    float dot = __fadd_rn(__fadd_rn(__fmul_rn(q.x, p.x), __fmul_rn(q.y, p.y)),
                          __fmul_rn(q.z, p.z));
    return __fsub_rn(__fadd_rn(q.w, p.w), __fmul_rn(2.0f, dot));
}

// take up to (K_ - found) lowest set bits of mask, in ascending order;
// lane r (r = lane - found) claims the (r+1)-th set bit. Warp-parallel.
__device__ __forceinline__ void extract_fns(unsigned mask, int base, int lane,
                                            int& found, int& my_idx) {
    int c = __popc(mask);
    if (c) {
        int take = K_ - found;
        if (take > c) take = c;
        int r = lane - found;
        if (r >= 0 && r < take) {
            my_idx = base + __fns(mask, 0, r + 1);
        }
        found += take;
    }
}

__global__ __launch_bounds__(256, 4) void sa_kernel(
    const float* __restrict__ feat,
    const int*   __restrict__ fps_idx,
    const float* __restrict__ W1,
    const float* __restrict__ b1,
    const float* __restrict__ W2,
    const float* __restrict__ b2,
    float*       __restrict__ out)
{
    // h1 staging: [warp][neighbor][channel] = 8*16*32*4B = 16KB/CTA
    __shared__ float h1s[8][K_][32];

    const unsigned FULL = 0xffffffffu;
    int lane = threadIdx.x & 31;
    int warp = threadIdx.x >> 5;

    // hoist this lane's weight columns into registers
    float w1r[6], w2r[32];
    #pragma unroll
    for (int i = 0; i < 6; i++)  w1r[i] = W1[i * 32 + lane];
    #pragma unroll
    for (int i = 0; i < 32; i++) w2r[i] = W2[i * 32 + lane];
    float b1r = b1[lane];
    float b2r = b2[lane];

    // persistent warp: steal two queries per atomic
    for (;;) {
        int idx0q;
        if (lane == 0) idx0q = (int)atomicAdd(&g_qctr, 2u);
        idx0q = __shfl_sync(FULL, idx0q, 0);
        if (idx0q >= NQ) break;

        #pragma unroll 1
        for (int qq = 0; qq < 2; qq++) {
            int qid = idx0q + qq;
            if (qid >= NQ) break;

            int b = qid >> 12;            // / M_ (4096)
            const float4* __restrict__ pts = g_pts + (size_t)b * N_;
            const float4* __restrict__ pl  = pts + lane;

            float4 q = pts[fps_idx[qid]];

            // ---- ball query: first K_ in-ball indices in ascending order ----
            int found  = 0;
            int my_idx = 0;               // lane k (k<K_) owns neighbor k
            for (int base = 0; base < N_; base += 256, pl += 256) {
                float4 p0 = pl[0];
                float4 p1 = pl[32];
                float4 p2 = pl[64];
                float4 p3 = pl[96];
                float4 p4 = pl[128];
                float4 p5 = pl[160];
                float4 p6 = pl[192];
                float4 p7 = pl[224];
                unsigned m0 = __ballot_sync(FULL, dist2(q, p0) <= R2);
                unsigned m1 = __ballot_sync(FULL, dist2(q, p1) <= R2);
                unsigned m2 = __ballot_sync(FULL, dist2(q, p2) <= R2);
                unsigned m3 = __ballot_sync(FULL, dist2(q, p3) <= R2);
                unsigned m4 = __ballot_sync(FULL, dist2(q, p4) <= R2);
                unsigned m5 = __ballot_sync(FULL, dist2(q, p5) <= R2);
                unsigned m6 = __ballot_sync(FULL, dist2(q, p6) <= R2);
                unsigned m7 = __ballot_sync(FULL, dist2(q, p7) <= R2);
                unsigned any = (m0 | m1) | (m2 | m3) | ((m4 | m5) | (m6 | m7));
                if (any) {
                    extract_fns(m0, base,       lane, found, my_idx);
                    extract_fns(m1, base +  32, lane, found, my_idx);
                    extract_fns(m2, base +  64, lane, found, my_idx);
                    extract_fns(m3, base +  96, lane, found, my_idx);
                    extract_fns(m4, base + 128, lane, found, my_idx);
                    extract_fns(m5, base + 160, lane, found, my_idx);
                    extract_fns(m6, base + 192, lane, found, my_idx);
                    extract_fns(m7, base + 224, lane, found, my_idx);
                    if (found >= K_) break;
                }
            }
            // pad missing neighbors with the first valid one (reference
            // semantics); found >= 1 always (query is in its own ball).
            int idx0 = __shfl_sync(FULL, my_idx, 0);
            if (lane >= found) my_idx = idx0;
            int kmax = found < K_ ? found : K_;  // dups can't change the max

            // ---- MLP phase 1: h1 per neighbor -> smem ----
            const float* __restrict__ featb = feat + (size_t)b * N_ * 3;

            __syncwarp();     // prior phase-2 reads done before overwrite
            #pragma unroll 1
            for (int k = 0; k < kmax; k++) {
                int g = __shfl_sync(FULL, my_idx, k);
                float4 p = pts[g];                 // broadcast load
                float f0 = featb[3 * g + 0];
                float f1 = featb[3 * g + 1];
                float f2 = featb[3 * g + 2];
                float i0 = p.x - q.x, i1 = p.y - q.y, i2 = p.z - q.z;

                float h1 = b1r;
                h1 += i0 * w1r[0];
                h1 += i1 * w1r[1];
                h1 += i2 * w1r[2];
                h1 += f0 * w1r[3];
                h1 += f1 * w1r[4];
                h1 += f2 * w1r[5];
                h1 = fmaxf(h1, 0.1f * h1);         // leaky relu
                h1s[warp][k][lane] = h1;
            }
            __syncwarp();

            // ---- MLP phase 2: h2 = W2^T h1 via LDS.128 broadcast ----
            float acc = -3.402823466e38f;
            #pragma unroll 1
            for (int k = 0; k < kmax; k++) {
                const float4* hp = (const float4*)h1s[warp][k];
                float a0 = b2r, a1 = 0.f, a2 = 0.f, a3 = 0.f;
                {
                    float4 v0 = hp[0], v1 = hp[1], v2 = hp[2], v3 = hp[3];
                    a0 = fmaf(v0.x, w2r[0],  a0);
                    a1 = fmaf(v0.y, w2r[1],  a1);
                    a2 = fmaf(v0.z, w2r[2],  a2);
                    a3 = fmaf(v0.w, w2r[3],  a3);
                    a0 = fmaf(v1.x, w2r[4],  a0);
                    a1 = fmaf(v1.y, w2r[5],  a1);
                    a2 = fmaf(v1.z, w2r[6],  a2);
                    a3 = fmaf(v1.w, w2r[7],  a3);
                    a0 = fmaf(v2.x, w2r[8],  a0);
                    a1 = fmaf(v2.y, w2r[9],  a1);
                    a2 = fmaf(v2.z, w2r[10], a2);
                    a3 = fmaf(v2.w, w2r[11], a3);
                    a0 = fmaf(v3.x, w2r[12], a0);
                    a1 = fmaf(v3.y, w2r[13], a1);
                    a2 = fmaf(v3.z, w2r[14], a2);
                    a3 = fmaf(v3.w, w2r[15], a3);
                }
                {
                    float4 v4 = hp[4], v5 = hp[5], v6 = hp[6], v7 = hp[7];
                    a0 = fmaf(v4.x, w2r[16], a0);
                    a1 = fmaf(v4.y, w2r[17], a1);
                    a2 = fmaf(v4.z, w2r[18], a2);
                    a3 = fmaf(v4.w, w2r[19], a3);
                    a0 = fmaf(v5.x, w2r[20], a0);
                    a1 = fmaf(v5.y, w2r[21], a1);
                    a2 = fmaf(v5.z, w2r[22], a2);
                    a3 = fmaf(v5.w, w2r[23], a3);
                    a0 = fmaf(v6.x, w2r[24], a0);
                    a1 = fmaf(v6.y, w2r[25], a1);
                    a2 = fmaf(v6.z, w2r[26], a2);
                    a3 = fmaf(v6.w, w2r[27], a3);
                    a0 = fmaf(v7.x, w2r[28], a0);
                    a1 = fmaf(v7.y, w2r[29], a1);
                    a2 = fmaf(v7.z, w2r[30], a2);
                    a3 = fmaf(v7.w, w2r[31], a3);
                }
                float h2 = (a0 + a1) + (a2 + a3);
                h2 = fmaxf(h2, 0.1f * h2);
                acc = fmaxf(acc, h2);
            }

            out[((size_t)qid) * 32 + lane] = acc;
        }
    }
}

extern "C" void kernel_launch(void* const* d_in, const int* in_sizes, int n_in,
                              void* d_out, int out_size) {
    const float* xyz     = (const float*)d_in[0];
    const float* feat    = (const float*)d_in[1];
    const int*   fps_idx = (const int*)  d_in[2];
    const float* W1      = (const float*)d_in[3];
    const float* b1      = (const float*)d_in[4];
    const float* W2      = (const float*)d_in[5];
    const float* b2      = (const float*)d_in[6];
    float* out = (float*)d_out;

    prep_kernel<<<(B_ * N_ + 255) / 256, 256>>>(xyz);
    // persistent kernel: 4 CTAs/SM, work-stealing queue
    sa_kernel<<<592, 256>>>(feat, fps_idx, W1, b1, W2, b2, out);
    (void)in_sizes; (void)n_in; (void)out_size;
}

// round 10
// speedup vs baseline: 1.3761x; 1.3761x over previous
#include <cuda_runtime.h>

#define B_  4
#define N_  16384
#define M_  4096
#define K_  16
#define R2  0.25f
#define NQ  (B_ * M_)
#define LONG_THRESH 4.0f   // |q|^2 above this => long scan, schedule first

// Scratch: (x, y, z, |p|^2) per point. 4*16384*16B = 1 MB.
__device__ float4       g_pts[B_ * N_];
__device__ unsigned int g_qctr;    // work-stealing queue head
__device__ unsigned int g_front;   // long-query segment fill
__device__ unsigned int g_back;    // short-query segment fill
__device__ int          g_order[NQ];

__global__ __launch_bounds__(256) void prep_kernel(const float* __restrict__ xyz) {
    int i = blockIdx.x * blockDim.x + threadIdx.x;
    if (i == 0) { g_qctr = 0; g_front = 0; g_back = 0; }   // graph-replay safe
    if (i < B_ * N_) {
        float x = xyz[3 * i + 0];
        float y = xyz[3 * i + 1];
        float z = xyz[3 * i + 2];
        // match jnp.sum(x**2,-1): (x*x + y*y) + z*z, no fma contraction
        float sq = __fadd_rn(__fadd_rn(__fmul_rn(x, x), __fmul_rn(y, y)), __fmul_rn(z, z));
        g_pts[i] = make_float4(x, y, z, sq);
    }
}

// LPT scheduling: long-scan queries (large |q|^2) go to the front of the
// queue, short ones to the back. Processing order doesn't affect results.
__global__ __launch_bounds__(256) void order_kernel(const int* __restrict__ fps_idx) {
    int qid = blockIdx.x * blockDim.x + threadIdx.x;
    if (qid >= NQ) return;
    int b = qid >> 12;
    float w = g_pts[(size_t)b * N_ + fps_idx[qid]].w;
    int pos;
    if (w > LONG_THRESH) pos = (int)atomicAdd(&g_front, 1u);
    else                 pos = NQ - 1 - (int)atomicAdd(&g_back, 1u);
    g_order[pos] = qid;
}

// DO NOT change: reproduces reference's expanded |q|^2+|p|^2-2qp arithmetic;
// determines boundary membership (rel_err).
__device__ __forceinline__ float dist2(float4 q, float4 p) {
    float dot = __fadd_rn(__fadd_rn(__fmul_rn(q.x, p.x), __fmul_rn(q.y, p.y)),
                          __fmul_rn(q.z, p.z));
    return __fsub_rn(__fadd_rn(q.w, p.w), __fmul_rn(2.0f, dot));
}

// take up to (K_ - found) lowest set bits of mask, in ascending order;
// lane r (r = lane - found) claims the (r+1)-th set bit. Warp-parallel.
__device__ __forceinline__ void extract_fns(unsigned mask, int base, int lane,
                                            int& found, int& my_idx) {
    int c = __popc(mask);
    if (c) {
        int take = K_ - found;
        if (take > c) take = c;
        int r = lane - found;
        if (r >= 0 && r < take) {
            my_idx = base + __fns(mask, 0, r + 1);
        }
        found += take;
    }
}

__global__ __launch_bounds__(256, 4) void sa_kernel(
    const float* __restrict__ feat,
    const int*   __restrict__ fps_idx,
    const float* __restrict__ W1,
    const float* __restrict__ b1,
    const float* __restrict__ W2,
    const float* __restrict__ b2,
    float*       __restrict__ out)
{
    const unsigned FULL = 0xffffffffu;
    int lane = threadIdx.x & 31;

    // hoist this lane's weight columns into registers (inner loops become
    // pure SHFL+FFMA, no LDS/LDG)
    float w1r[6], w2r[32];
    #pragma unroll
    for (int i = 0; i < 6; i++)  w1r[i] = W1[i * 32 + lane];
    #pragma unroll
    for (int i = 0; i < 32; i++) w2r[i] = W2[i * 32 + lane];
    float b1r = b1[lane];
    float b2r = b2[lane];

    // persistent warp: steal one query at a time, longest-first order
    for (;;) {
        int idx;
        if (lane == 0) idx = (int)atomicAdd(&g_qctr, 1u);
        idx = __shfl_sync(FULL, idx, 0);
        if (idx >= NQ) break;
        int qid = g_order[idx];

        int b = qid >> 12;            // / M_ (4096)
        const float4* __restrict__ pts = g_pts + (size_t)b * N_;
        const float4* __restrict__ pl  = pts + lane;

        float4 q = pts[fps_idx[qid]];

        // ---- ball query: first K_ in-ball indices in ascending order ----
        // 8 independent 16B loads (256 points) in flight before the exit check.
        int found  = 0;
        int my_idx = 0;               // lane k (k<K_) owns neighbor k
        for (int base = 0; base < N_; base += 256, pl += 256) {
            float4 p0 = pl[0];
            float4 p1 = pl[32];
            float4 p2 = pl[64];
            float4 p3 = pl[96];
            float4 p4 = pl[128];
            float4 p5 = pl[160];
            float4 p6 = pl[192];
            float4 p7 = pl[224];
            unsigned m0 = __ballot_sync(FULL, dist2(q, p0) <= R2);
            unsigned m1 = __ballot_sync(FULL, dist2(q, p1) <= R2);
            unsigned m2 = __ballot_sync(FULL, dist2(q, p2) <= R2);
            unsigned m3 = __ballot_sync(FULL, dist2(q, p3) <= R2);
            unsigned m4 = __ballot_sync(FULL, dist2(q, p4) <= R2);
            unsigned m5 = __ballot_sync(FULL, dist2(q, p5) <= R2);
            unsigned m6 = __ballot_sync(FULL, dist2(q, p6) <= R2);
            unsigned m7 = __ballot_sync(FULL, dist2(q, p7) <= R2);
            unsigned any = (m0 | m1) | (m2 | m3) | ((m4 | m5) | (m6 | m7));
            if (any) {
                extract_fns(m0, base,       lane, found, my_idx);
                extract_fns(m1, base +  32, lane, found, my_idx);
                extract_fns(m2, base +  64, lane, found, my_idx);
                extract_fns(m3, base +  96, lane, found, my_idx);
                extract_fns(m4, base + 128, lane, found, my_idx);
                extract_fns(m5, base + 160, lane, found, my_idx);
                extract_fns(m6, base + 192, lane, found, my_idx);
                extract_fns(m7, base + 224, lane, found, my_idx);
                if (found >= K_) break;
            }
        }
        // pad missing neighbors with the first valid one (reference
        // semantics); found >= 1 always (query is in its own ball).
        int idx0 = __shfl_sync(FULL, my_idx, 0);
        if (lane >= found) my_idx = idx0;
        int kmax = found < K_ ? found : K_;   // padded dups can't change max

        // ---- MLP + maxpool: lane j owns output channel j ----
        const float* __restrict__ featb = feat + (size_t)b * N_ * 3;
        float acc = -3.402823466e38f;

        #pragma unroll 1
        for (int k = 0; k < kmax; k++) {
            int g = __shfl_sync(FULL, my_idx, k);
            float4 p = pts[g];                    // broadcast load (L1/L2 hit)
            float f0 = featb[3 * g + 0];
            float f1 = featb[3 * g + 1];
            float f2 = featb[3 * g + 2];
            float i0 = p.x - q.x, i1 = p.y - q.y, i2 = p.z - q.z;

            float h1 = b1r;
            h1 += i0 * w1r[0];
            h1 += i1 * w1r[1];
            h1 += i2 * w1r[2];
            h1 += f0 * w1r[3];
            h1 += f1 * w1r[4];
            h1 += f2 * w1r[5];
            h1 = fmaxf(h1, 0.1f * h1);            // leaky relu

            // 4 accumulator chains to break the serial FMA dependency
            float a0 = b2r, a1 = 0.f, a2 = 0.f, a3 = 0.f;
            #pragma unroll
            for (int i = 0; i < 32; i += 4) {
                a0 = fmaf(__shfl_sync(FULL, h1, i + 0), w2r[i + 0], a0);
                a1 = fmaf(__shfl_sync(FULL, h1, i + 1), w2r[i + 1], a1);
                a2 = fmaf(__shfl_sync(FULL, h1, i + 2), w2r[i + 2], a2);
                a3 = fmaf(__shfl_sync(FULL, h1, i + 3), w2r[i + 3], a3);
            }
            float h2 = (a0 + a1) + (a2 + a3);
            h2 = fmaxf(h2, 0.1f * h2);

            acc = fmaxf(acc, h2);
        }

        out[((size_t)qid) * 32 + lane] = acc;
    }
}

extern "C" void kernel_launch(void* const* d_in, const int* in_sizes, int n_in,
                              void* d_out, int out_size) {
    const float* xyz     = (const float*)d_in[0];
    const float* feat    = (const float*)d_in[1];
    const int*   fps_idx = (const int*)  d_in[2];
    const float* W1      = (const float*)d_in[3];
    const float* b1      = (const float*)d_in[4];
    const float* W2      = (const float*)d_in[5];
    const float* b2      = (const float*)d_in[6];
    float* out = (float*)d_out;

    prep_kernel<<<(B_ * N_ + 255) / 256, 256>>>(xyz);
    order_kernel<<<NQ / 256, 256>>>(fps_idx);
    // persistent kernel: 4 CTAs/SM, work-stealing queue, longest-first
    sa_kernel<<<592, 256>>>(feat, fps_idx, W1, b1, W2, b2, out);
    (void)in_sizes; (void)n_in; (void)out_size;
}